// round 12
// baseline (speedup 1.0000x reference)
#include <cuda_runtime.h>
#include <cuda_bf16.h>
#include <math.h>
#include <stdint.h>

#define DIM   768
#define QKV3  2304
#define HID   3072
#define ROWS  8192      // 4 * 2048
#define SEQ   2048
#define NH    12
#define HD    64

// ---------------- scratch (bf16 hi/lo pairs + fp32 where needed) ------------
__device__ __align__(256) __nv_bfloat16 g_lnh [ROWS * DIM];
__device__ __align__(256) __nv_bfloat16 g_lnl [ROWS * DIM];
__device__ __align__(256) float         g_qkv [ROWS * QKV3];
__device__ __align__(256) __nv_bfloat16 g_atth[ROWS * DIM];
__device__ __align__(256) __nv_bfloat16 g_attl[ROWS * DIM];
__device__ __align__(256) float         g_res [ROWS * DIM];
__device__ __align__(256) __nv_bfloat16 g_hh  [ROWS * HID];
__device__ __align__(256) __nv_bfloat16 g_hl  [ROWS * HID];
// split weights (separate buffers so all converts run up front)
__device__ __align__(256) __nv_bfloat16 g_qwh [QKV3 * DIM];
__device__ __align__(256) __nv_bfloat16 g_qwl [QKV3 * DIM];
__device__ __align__(256) __nv_bfloat16 g_pwh [DIM * DIM];
__device__ __align__(256) __nv_bfloat16 g_pwl [DIM * DIM];
__device__ __align__(256) __nv_bfloat16 g_f1h [HID * DIM];
__device__ __align__(256) __nv_bfloat16 g_f1l [HID * DIM];
__device__ __align__(256) __nv_bfloat16 g_f2h [DIM * HID];
__device__ __align__(256) __nv_bfloat16 g_f2l [DIM * HID];

// ---------------- helpers ---------------------------------------------------
__device__ __forceinline__ uint32_t smem_u32(const void* p) {
    uint32_t a;
    asm("{ .reg .u64 t; cvta.to.shared.u64 t, %1; cvt.u32.u64 %0, t; }"
        : "=r"(a) : "l"(p));
    return a;
}

__device__ __forceinline__ void ldsm4(uint32_t* r, uint32_t addr) {
    asm volatile("ldmatrix.sync.aligned.m8n8.x4.shared.b16 {%0,%1,%2,%3}, [%4];"
                 : "=r"(r[0]), "=r"(r[1]), "=r"(r[2]), "=r"(r[3]) : "r"(addr));
}

__device__ __forceinline__ void mma16816(float* c, const uint32_t* a,
                                         const uint32_t* b) {
    asm volatile(
        "mma.sync.aligned.m16n8k16.row.col.f32.bf16.bf16.f32 "
        "{%0,%1,%2,%3}, {%4,%5,%6,%7}, {%8,%9}, {%0,%1,%2,%3};"
        : "+f"(c[0]), "+f"(c[1]), "+f"(c[2]), "+f"(c[3])
        : "r"(a[0]), "r"(a[1]), "r"(a[2]), "r"(a[3]), "r"(b[0]), "r"(b[1]));
}

__device__ __forceinline__ uint32_t hipack(float x, float y) {
    return (__float_as_uint(x) >> 16) | (__float_as_uint(y) & 0xFFFF0000u);
}
__device__ __forceinline__ uint32_t lopack(float x, float y) {
    float rx = x - __uint_as_float(__float_as_uint(x) & 0xFFFF0000u);
    float ry = y - __uint_as_float(__float_as_uint(y) & 0xFFFF0000u);
    uint32_t r;
    asm("cvt.rn.bf16x2.f32 %0, %1, %2;" : "=r"(r) : "f"(ry), "f"(rx));
    return r;
}
__device__ __forceinline__ void split4(const float4 v, uint2& h, uint2& l) {
    h.x = hipack(v.x, v.y);
    h.y = hipack(v.z, v.w);
    l.x = lopack(v.x, v.y);
    l.y = lopack(v.z, v.w);
}

#define CP_ASYNC16(dst, src) \
    asm volatile("cp.async.cg.shared.global [%0], [%1], 16;" \
                 :: "r"(dst), "l"(src))
#define CP_COMMIT() asm volatile("cp.async.commit_group;" ::: "memory")
#define CP_WAIT(n)  asm volatile("cp.async.wait_group %0;" :: "n"(n) : "memory")

// ---------------- weight split: fp32 -> bf16 hi/lo ---------------------------
__global__ void __launch_bounds__(256) convert_w(
    const float* __restrict__ w, __nv_bfloat16* __restrict__ wh,
    __nv_bfloat16* __restrict__ wl, int n4)
{
    int i = blockIdx.x * 256 + threadIdx.x;
    if (i >= n4) return;
    float4 v = ((const float4*)w)[i];
    uint2 h, l;
    split4(v, h, l);
    ((uint2*)wh)[i] = h;
    ((uint2*)wl)[i] = l;
}

// ---------------- LayerNorm -> split bf16 output -----------------------------
__global__ void __launch_bounds__(256) ln_split(
    const float* __restrict__ x, const float* __restrict__ w,
    const float* __restrict__ b, __nv_bfloat16* __restrict__ oh,
    __nv_bfloat16* __restrict__ ol)
{
    const int row = blockIdx.x;
    const float* xr = x + (size_t)row * DIM;
    const size_t base = (size_t)row * DIM;
    const int t = threadIdx.x;

    float v0 = xr[t], v1 = xr[t + 256], v2 = xr[t + 512];
    float s  = v0 + v1 + v2;
    float ss = v0 * v0 + v1 * v1 + v2 * v2;

    __shared__ float red[16];
    #pragma unroll
    for (int o = 16; o > 0; o >>= 1) {
        s  += __shfl_xor_sync(0xffffffffu, s,  o);
        ss += __shfl_xor_sync(0xffffffffu, ss, o);
    }
    const int lane = t & 31, wid = t >> 5;
    if (lane == 0) { red[wid] = s; red[8 + wid] = ss; }
    __syncthreads();
    if (t == 0) {
        float a = 0.f, c = 0.f;
        #pragma unroll
        for (int i = 0; i < 8; i++) { a += red[i]; c += red[8 + i]; }
        float mean = a * (1.0f / DIM);
        float var  = c * (1.0f / DIM) - mean * mean;
        red[0] = mean;
        red[1] = rsqrtf(var + 1e-5f);
    }
    __syncthreads();
    const float mean = red[0], rstd = red[1];
    #pragma unroll
    for (int u = 0; u < 3; u++) {
        const int col = t + u * 256;
        const float v = (u == 0 ? v0 : (u == 1 ? v1 : v2));
        float y = (v - mean) * rstd * w[col] + b[col];
        uint32_t bits = __float_as_uint(y);
        ((uint16_t*)oh)[base + col] = (uint16_t)(bits >> 16);
        float rem = y - __uint_as_float(bits & 0xFFFF0000u);
        ol[base + col] = __float2bfloat16(rem);
    }
}

// ---------------- cp.async HMMA split GEMM-NT --------------------------------
// C = A @ W^T + bias (+R fp32) (+GELU); A,W given as bf16 hi/lo in gmem.
// CTA 128x128, BK=32, 3-stage cp.async pipeline, 8 warps (4m x 2n).
#define CP_PITCH 80u
#define CP_TILE  (128u * CP_PITCH)     // 10240
#define CP_STAGE (4u * CP_TILE)        // Ah Al Wh Wl = 40960
#define CP_SMEM  (3u * CP_STAGE)       // 122880

// OUTS: 0 = fp32 C, 1 = split bf16 Ch/Cl
template <int ACT, int RES, int OUTS>
__global__ void __launch_bounds__(256, 1) gemm_cp(
    const __nv_bfloat16* __restrict__ Ah, const __nv_bfloat16* __restrict__ Al,
    const __nv_bfloat16* __restrict__ Wh, const __nv_bfloat16* __restrict__ Wl,
    const float* __restrict__ bias, const float* __restrict__ R,
    float* __restrict__ C, __nv_bfloat16* __restrict__ Ch,
    __nv_bfloat16* __restrict__ Cl, int M, int N, int K)
{
    extern __shared__ __align__(16) char sm[];
    const uint32_t sb = smem_u32(sm);

    const int t    = threadIdx.x;
    const int lane = t & 31, wid = t >> 5;
    const int mw   = wid & 3, nw = wid >> 2;
    const int m0   = blockIdx.y * 128, n0 = blockIdx.x * 128;
    const int NC   = K >> 5;

    const int lrow = (t >> 2);        // 0..63
    const int lc   = t & 3;           // 16B chunk within 64B row

    // per-u tile sources: u>>1 = 0:Ah 1:Al 2:Wh 3:Wl ; row = lrow + (u&1)*64
    const __nv_bfloat16* srcs[4] = {
        Ah + (size_t)m0 * K, Al + (size_t)m0 * K,
        Wh + (size_t)n0 * K, Wl + (size_t)n0 * K };

    auto issue = [&](uint32_t sbase, int kc) {
        #pragma unroll
        for (int u = 0; u < 8; u++) {
            const int tile = u >> 1;
            const int row  = lrow + (u & 1) * 64;
            const __nv_bfloat16* src =
                srcs[tile] + (size_t)row * K + kc + lc * 8;
            uint32_t dst = sbase + tile * CP_TILE
                         + (uint32_t)row * CP_PITCH + lc * 16;
            CP_ASYNC16(dst, src);
        }
    };

    float cfr[2][8][4];
    #pragma unroll
    for (int i = 0; i < 2; i++)
        #pragma unroll
        for (int j = 0; j < 8; j++)
            #pragma unroll
            for (int k = 0; k < 4; k++) cfr[i][j][k] = 0.f;

    const uint32_t stg[3] = { sb, sb + CP_STAGE, sb + 2 * CP_STAGE };
    issue(stg[0], 0);  CP_COMMIT();
    issue(stg[1], 32); CP_COMMIT();

    const uint32_t a_lane = (uint32_t)(mw * 32 + (lane & 15)) * CP_PITCH
                          + ((lane >> 4) * 16);
    const uint32_t b_lane = (uint32_t)(nw * 64 + (lane & 7)
                          + (((lane >> 4) & 1) * 8)) * CP_PITCH
                          + (((lane >> 3) & 1) * 16);

    for (int c = 0; c < NC; c++) {
        CP_WAIT(1);
        __syncthreads();

        const uint32_t stage = stg[c % 3];
        #pragma unroll
        for (int ks = 0; ks < 2; ks++) {
            uint32_t ah[2][4], al[2][4];
            #pragma unroll
            for (int mt = 0; mt < 2; mt++) {
                uint32_t aoff = a_lane + (uint32_t)mt * (16 * CP_PITCH)
                              + ks * 32;
                ldsm4(ah[mt], stage + aoff);
                ldsm4(al[mt], stage + CP_TILE + aoff);
            }
            #pragma unroll
            for (int p = 0; p < 4; p++) {
                uint32_t bh[4], bl[4];
                uint32_t boff = b_lane + (uint32_t)p * (16 * CP_PITCH)
                              + ks * 32;
                ldsm4(bh, stage + 2 * CP_TILE + boff);
                ldsm4(bl, stage + 3 * CP_TILE + boff);
                #pragma unroll
                for (int mt = 0; mt < 2; mt++) {
                    #pragma unroll
                    for (int q = 0; q < 2; q++) {
                        float* cc = cfr[mt][2 * p + q];
                        mma16816(cc, ah[mt], &bh[q * 2]);
                        mma16816(cc, ah[mt], &bl[q * 2]);
                        mma16816(cc, al[mt], &bh[q * 2]);
                    }
                }
            }
        }

        if (c + 2 < NC) issue(stg[(c + 2) % 3], (c + 2) * 32);
        CP_COMMIT();
    }

    // ---- epilogue ----
    const int er0 = m0 + mw * 32 + (lane >> 2);
    const int ec0 = n0 + nw * 64 + (lane & 3) * 2;
    #pragma unroll
    for (int mt = 0; mt < 2; mt++) {
        #pragma unroll
        for (int nt = 0; nt < 8; nt++) {
            const int col = ec0 + nt * 8;
            const float2 bv = *(const float2*)(bias + col);
            #pragma unroll
            for (int half = 0; half < 2; half++) {
                const int row = er0 + mt * 16 + half * 8;
                const size_t off = (size_t)row * N + col;
                float vx = cfr[mt][nt][half * 2 + 0] + bv.x;
                float vy = cfr[mt][nt][half * 2 + 1] + bv.y;
                if (RES) {
                    const float2 rv = *(const float2*)(R + off);
                    vx += rv.x; vy += rv.y;
                }
                if (ACT) {
                    vx = 0.5f * vx * (1.0f + erff(vx * 0.70710678118654752f));
                    vy = 0.5f * vy * (1.0f + erff(vy * 0.70710678118654752f));
                }
                if (OUTS == 0) {
                    *(float2*)(C + off) = make_float2(vx, vy);
                } else {
                    *(uint32_t*)(Ch + off) = hipack(vx, vy);
                    *(uint32_t*)(Cl + off) = lopack(vx, vy);
                }
            }
        }
    }
}

// ---------------- HMMA flash attention (bf16 hi/lo split) -------------------
#define FP_P    144u
#define FQ_H    0u
#define FQ_L    (FQ_H + 128u * FP_P)
#define FK_H    (FQ_L + 128u * FP_P)
#define FK_L    (FK_H + 64u * FP_P)
#define FV_H    (FK_L + 64u * FP_P)
#define FV_L    (FV_H + 64u * FP_P)
#define FL_SMEM (FV_L + 64u * FP_P)        // 73728

__global__ void __launch_bounds__(256, 1) flash_mma(
    const float* __restrict__ qkv, __nv_bfloat16* __restrict__ atth,
    __nv_bfloat16* __restrict__ attl)
{
    extern __shared__ __align__(16) char sm[];
    const uint32_t sb = smem_u32(sm);

    const int bh = blockIdx.y;
    const int b  = bh / NH, h = bh % NH;
    const int q0 = blockIdx.x * 128;
    const int t  = threadIdx.x, lane = t & 31, wid = t >> 5;

    #pragma unroll
    for (int u = 0; u < 8; u++) {
        int i = t + u * 256, row = i >> 4, c4 = i & 15;
        float4 v = *(const float4*)(qkv + (size_t)(b * SEQ + q0 + row) * QKV3
                                    + h * HD + c4 * 4);
        uint2 hh, ll;
        split4(v, hh, ll);
        uint32_t off = (uint32_t)row * FP_P + c4 * 8;
        *(uint2*)(sm + FQ_H + off) = hh;
        *(uint2*)(sm + FQ_L + off) = ll;
    }

    float4 rk[4], rv[4];
    {
        #pragma unroll
        for (int u = 0; u < 4; u++) {
            int i = t + u * 256, key = i >> 4, c4 = i & 15;
            const size_t rowb = (size_t)(b * SEQ + key) * QKV3 + h * HD + c4 * 4;
            rk[u] = *(const float4*)(qkv + rowb + DIM);
            rv[u] = *(const float4*)(qkv + rowb + 2 * DIM);
        }
    }
    __syncthreads();

    uint32_t qh[4][4], ql[4][4];
    {
        const uint32_t a_lane = (uint32_t)(wid * 16 + (lane & 15)) * FP_P
                              + ((lane >> 4) * 16);
        #pragma unroll
        for (int ks = 0; ks < 4; ks++) {
            ldsm4(qh[ks], sb + FQ_H + a_lane + ks * 32);
            ldsm4(ql[ks], sb + FQ_L + a_lane + ks * 32);
        }
    }

    #pragma unroll
    for (int u = 0; u < 4; u++) {
        int i = t + u * 256, key = i >> 4, c4 = i & 15;
        uint2 hh, ll;
        split4(rk[u], hh, ll);
        uint32_t off = (uint32_t)key * FP_P + c4 * 8;
        *(uint2*)(sm + FK_H + off) = hh;
        *(uint2*)(sm + FK_L + off) = ll;
        const float vv[4] = { rv[u].x, rv[u].y, rv[u].z, rv[u].w };
        #pragma unroll
        for (int j = 0; j < 4; j++) {
            int d = c4 * 4 + j;
            uint32_t bits = __float_as_uint(vv[j]);
            *(uint16_t*)(sm + FV_H + (uint32_t)d * FP_P + key * 2) =
                (uint16_t)(bits >> 16);
            float rem = vv[j] - __uint_as_float(bits & 0xFFFF0000u);
            *(__nv_bfloat16*)(sm + FV_L + (uint32_t)d * FP_P + key * 2) =
                __float2bfloat16(rem);
        }
    }
    __syncthreads();

    float mr1 = -1e30f, mr2 = -1e30f, lr1 = 0.f, lr2 = 0.f;
    float o[8][4];
    #pragma unroll
    for (int f = 0; f < 8; f++)
        #pragma unroll
        for (int j = 0; j < 4; j++) o[f][j] = 0.f;

    const uint32_t bK = (uint32_t)((lane & 7) + ((lane >> 4) & 1) * 8) * FP_P
                      + ((lane >> 3) & 1) * 16;

    const int NT = SEQ / 64;
    for (int c = 0; c < NT; c++) {
        if (c + 1 < NT) {
            const int k0 = (c + 1) * 64;
            #pragma unroll
            for (int u = 0; u < 4; u++) {
                int i = t + u * 256, key = i >> 4, c4 = i & 15;
                const size_t rowb = (size_t)(b * SEQ + k0 + key) * QKV3
                                  + h * HD + c4 * 4;
                rk[u] = *(const float4*)(qkv + rowb + DIM);
                rv[u] = *(const float4*)(qkv + rowb + 2 * DIM);
            }
        }

        float sf[8][4];
        #pragma unroll
        for (int f = 0; f < 8; f++)
            #pragma unroll
            for (int j = 0; j < 4; j++) sf[f][j] = 0.f;

        #pragma unroll
        for (int p = 0; p < 4; p++) {
            #pragma unroll
            for (int ks = 0; ks < 4; ks++) {
                uint32_t bhf[4], blf[4];
                uint32_t boff = bK + (uint32_t)p * (16 * FP_P) + ks * 32;
                ldsm4(bhf, sb + FK_H + boff);
                ldsm4(blf, sb + FK_L + boff);
                #pragma unroll
                for (int q = 0; q < 2; q++) {
                    float* cc = sf[2 * p + q];
                    mma16816(cc, qh[ks], &bhf[q * 2]);
                    mma16816(cc, qh[ks], &blf[q * 2]);
                    mma16816(cc, ql[ks], &bhf[q * 2]);
                }
            }
        }

        float m1 = -1e30f, m2 = -1e30f;
        #pragma unroll
        for (int f = 0; f < 8; f++) {
            sf[f][0] *= 0.125f; sf[f][1] *= 0.125f;
            sf[f][2] *= 0.125f; sf[f][3] *= 0.125f;
            m1 = fmaxf(m1, fmaxf(sf[f][0], sf[f][1]));
            m2 = fmaxf(m2, fmaxf(sf[f][2], sf[f][3]));
        }
        m1 = fmaxf(m1, __shfl_xor_sync(0xffffffffu, m1, 1));
        m1 = fmaxf(m1, __shfl_xor_sync(0xffffffffu, m1, 2));
        m2 = fmaxf(m2, __shfl_xor_sync(0xffffffffu, m2, 1));
        m2 = fmaxf(m2, __shfl_xor_sync(0xffffffffu, m2, 2));

        const float mn1 = fmaxf(mr1, m1), mn2 = fmaxf(mr2, m2);
        const float corr1 = __expf(mr1 - mn1), corr2 = __expf(mr2 - mn2);
        float r1 = 0.f, r2 = 0.f;
        #pragma unroll
        for (int f = 0; f < 8; f++) {
            sf[f][0] = __expf(sf[f][0] - mn1);
            sf[f][1] = __expf(sf[f][1] - mn1);
            sf[f][2] = __expf(sf[f][2] - mn2);
            sf[f][3] = __expf(sf[f][3] - mn2);
            r1 += sf[f][0] + sf[f][1];
            r2 += sf[f][2] + sf[f][3];
        }
        r1 += __shfl_xor_sync(0xffffffffu, r1, 1);
        r1 += __shfl_xor_sync(0xffffffffu, r1, 2);
        r2 += __shfl_xor_sync(0xffffffffu, r2, 1);
        r2 += __shfl_xor_sync(0xffffffffu, r2, 2);
        lr1 = lr1 * corr1 + r1;
        lr2 = lr2 * corr2 + r2;
        mr1 = mn1; mr2 = mn2;
        #pragma unroll
        for (int f = 0; f < 8; f++) {
            o[f][0] *= corr1; o[f][1] *= corr1;
            o[f][2] *= corr2; o[f][3] *= corr2;
        }

        #pragma unroll
        for (int ks2 = 0; ks2 < 4; ks2++) {
            const int f = 2 * ks2;
            uint32_t ph[4], pl[4];
            ph[0] = hipack(sf[f][0],     sf[f][1]);
            ph[1] = hipack(sf[f][2],     sf[f][3]);
            ph[2] = hipack(sf[f + 1][0], sf[f + 1][1]);
            ph[3] = hipack(sf[f + 1][2], sf[f + 1][3]);
            pl[0] = lopack(sf[f][0],     sf[f][1]);
            pl[1] = lopack(sf[f][2],     sf[f][3]);
            pl[2] = lopack(sf[f + 1][0], sf[f + 1][1]);
            pl[3] = lopack(sf[f + 1][2], sf[f + 1][3]);
            #pragma unroll
            for (int p = 0; p < 4; p++) {
                uint32_t vh[4], vl[4];
                uint32_t boff = bK + (uint32_t)p * (16 * FP_P) + ks2 * 32;
                ldsm4(vh, sb + FV_H + boff);
                ldsm4(vl, sb + FV_L + boff);
                #pragma unroll
                for (int q = 0; q < 2; q++) {
                    float* cc = o[2 * p + q];
                    mma16816(cc, ph, &vh[q * 2]);
                    mma16816(cc, ph, &vl[q * 2]);
                    mma16816(cc, pl, &vh[q * 2]);
                }
            }
        }
        __syncthreads();

        if (c + 1 < NT) {
            #pragma unroll
            for (int u = 0; u < 4; u++) {
                int i = t + u * 256, key = i >> 4, c4 = i & 15;
                uint2 hh, ll;
                split4(rk[u], hh, ll);
                uint32_t off = (uint32_t)key * FP_P + c4 * 8;
                *(uint2*)(sm + FK_H + off) = hh;
                *(uint2*)(sm + FK_L + off) = ll;
                const float vv[4] = { rv[u].x, rv[u].y, rv[u].z, rv[u].w };
                #pragma unroll
                for (int j = 0; j < 4; j++) {
                    int d = c4 * 4 + j;
                    uint32_t bits = __float_as_uint(vv[j]);
                    *(uint16_t*)(sm + FV_H + (uint32_t)d * FP_P + key * 2) =
                        (uint16_t)(bits >> 16);
                    float rem = vv[j] - __uint_as_float(bits & 0xFFFF0000u);
                    *(__nv_bfloat16*)(sm + FV_L + (uint32_t)d * FP_P + key * 2) =
                        __float2bfloat16(rem);
                }
            }
            __syncthreads();
        }
    }

    // ---- write split att output ----
    const float il1 = 1.0f / lr1, il2 = 1.0f / lr2;
    const int row1 = b * SEQ + q0 + wid * 16 + (lane >> 2);
    #pragma unroll
    for (int f = 0; f < 8; f++) {
        const int col = h * HD + f * 8 + (lane & 3) * 2;
        const size_t o1 = (size_t)row1 * DIM + col;
        const size_t o2 = (size_t)(row1 + 8) * DIM + col;
        float ax = o[f][0] * il1, ay = o[f][1] * il1;
        float bx = o[f][2] * il2, by = o[f][3] * il2;
        *(uint32_t*)(atth + o1) = hipack(ax, ay);
        *(uint32_t*)(attl + o1) = lopack(ax, ay);
        *(uint32_t*)(atth + o2) = hipack(bx, by);
        *(uint32_t*)(attl + o2) = lopack(bx, by);
    }
}

// ---------------------------------------------------------------------------
extern "C" void kernel_launch(void* const* d_in, const int* in_sizes, int n_in,
                              void* d_out, int out_size)
{
    const float* x      = (const float*)d_in[0];
    const float* ln1_w  = (const float*)d_in[1];
    const float* ln1_b  = (const float*)d_in[2];
    const float* qkv_w  = (const float*)d_in[3];
    const float* qkv_b  = (const float*)d_in[4];
    const float* proj_w = (const float*)d_in[5];
    const float* proj_b = (const float*)d_in[6];
    const float* ln2_w  = (const float*)d_in[7];
    const float* ln2_b  = (const float*)d_in[8];
    const float* fc1_w  = (const float*)d_in[9];
    const float* fc1_b  = (const float*)d_in[10];
    const float* fc2_w  = (const float*)d_in[11];
    const float* fc2_b  = (const float*)d_in[12];
    float* out = (float*)d_out;

    float *p_qkv, *p_res;
    __nv_bfloat16 *p_lnh, *p_lnl, *p_atth, *p_attl, *p_hh, *p_hl;
    __nv_bfloat16 *p_qwh, *p_qwl, *p_pwh, *p_pwl, *p_f1h, *p_f1l, *p_f2h, *p_f2l;
    cudaGetSymbolAddress((void**)&p_qkv,  g_qkv);
    cudaGetSymbolAddress((void**)&p_res,  g_res);
    cudaGetSymbolAddress((void**)&p_lnh,  g_lnh);
    cudaGetSymbolAddress((void**)&p_lnl,  g_lnl);
    cudaGetSymbolAddress((void**)&p_atth, g_atth);
    cudaGetSymbolAddress((void**)&p_attl, g_attl);
    cudaGetSymbolAddress((void**)&p_hh,   g_hh);
    cudaGetSymbolAddress((void**)&p_hl,   g_hl);
    cudaGetSymbolAddress((void**)&p_qwh,  g_qwh);
    cudaGetSymbolAddress((void**)&p_qwl,  g_qwl);
    cudaGetSymbolAddress((void**)&p_pwh,  g_pwh);
    cudaGetSymbolAddress((void**)&p_pwl,  g_pwl);
    cudaGetSymbolAddress((void**)&p_f1h,  g_f1h);
    cudaGetSymbolAddress((void**)&p_f1l,  g_f1l);
    cudaGetSymbolAddress((void**)&p_f2h,  g_f2h);
    cudaGetSymbolAddress((void**)&p_f2l,  g_f2l);

    cudaFuncSetAttribute(flash_mma,
                         cudaFuncAttributeMaxDynamicSharedMemorySize, FL_SMEM);
    cudaFuncSetAttribute(gemm_cp<0, 0, 0>,
                         cudaFuncAttributeMaxDynamicSharedMemorySize, CP_SMEM);
    cudaFuncSetAttribute(gemm_cp<0, 1, 0>,
                         cudaFuncAttributeMaxDynamicSharedMemorySize, CP_SMEM);
    cudaFuncSetAttribute(gemm_cp<1, 0, 1>,
                         cudaFuncAttributeMaxDynamicSharedMemorySize, CP_SMEM);

    // 0) split all weights up-front
    {
        int n4;
        n4 = QKV3 * DIM / 4;
        convert_w<<<(n4 + 255) / 256, 256>>>(qkv_w, p_qwh, p_qwl, n4);
        n4 = DIM * DIM / 4;
        convert_w<<<(n4 + 255) / 256, 256>>>(proj_w, p_pwh, p_pwl, n4);
        n4 = HID * DIM / 4;
        convert_w<<<(n4 + 255) / 256, 256>>>(fc1_w, p_f1h, p_f1l, n4);
        n4 = DIM * HID / 4;
        convert_w<<<(n4 + 255) / 256, 256>>>(fc2_w, p_f2h, p_f2l, n4);
    }

    // 1) ln1(x) -> split
    ln_split<<<ROWS, 256>>>(x, ln1_w, ln1_b, p_lnh, p_lnl);
    // 2) qkv = ln1 @ qkv_w^T + qkv_b -> fp32 (flash input)
    gemm_cp<0, 0, 0><<<dim3(QKV3 / 128, ROWS / 128), 256, CP_SMEM>>>(
        p_lnh, p_lnl, p_qwh, p_qwl, qkv_b, nullptr,
        p_qkv, nullptr, nullptr, ROWS, QKV3, DIM);
    // 3) attention -> split att
    flash_mma<<<dim3(SEQ / 128, 4 * NH), 256, FL_SMEM>>>(p_qkv, p_atth, p_attl);
    // 4) x1 = att @ proj_w^T + proj_b + x -> fp32 res
    gemm_cp<0, 1, 0><<<dim3(DIM / 128, ROWS / 128), 256, CP_SMEM>>>(
        p_atth, p_attl, p_pwh, p_pwl, proj_b, x,
        p_res, nullptr, nullptr, ROWS, DIM, DIM);
    // 5) ln2(x1) -> split
    ln_split<<<ROWS, 256>>>(p_res, ln2_w, ln2_b, p_lnh, p_lnl);
    // 6) h = gelu(ln2 @ fc1_w^T + fc1_b) -> split
    gemm_cp<1, 0, 1><<<dim3(HID / 128, ROWS / 128), 256, CP_SMEM>>>(
        p_lnh, p_lnl, p_f1h, p_f1l, fc1_b, nullptr,
        nullptr, p_hh, p_hl, ROWS, HID, DIM);
    // 7) out = h @ fc2_w^T + fc2_b + x1
    gemm_cp<0, 1, 0><<<dim3(DIM / 128, ROWS / 128), 256, CP_SMEM>>>(
        p_hh, p_hl, p_f2h, p_f2l, fc2_b, p_res,
        out, nullptr, nullptr, ROWS, DIM, HID);
}

// round 13
// speedup vs baseline: 1.1207x; 1.1207x over previous
#include <cuda_runtime.h>
#include <cuda_bf16.h>
#include <math.h>
#include <stdint.h>

#define DIM   768
#define QKV3  2304
#define HID   3072
#define ROWS  8192      // 4 * 2048
#define SEQ   2048
#define NH    12
#define HD    64

// ---------------- scratch (bf16 hi/lo pairs + fp32 where needed) ------------
__device__ __align__(256) __nv_bfloat16 g_lnh [ROWS * DIM];
__device__ __align__(256) __nv_bfloat16 g_lnl [ROWS * DIM];
__device__ __align__(256) float         g_qkv [ROWS * QKV3];
__device__ __align__(256) __nv_bfloat16 g_atth[ROWS * DIM];
__device__ __align__(256) __nv_bfloat16 g_attl[ROWS * DIM];
__device__ __align__(256) float         g_res [ROWS * DIM];
__device__ __align__(256) __nv_bfloat16 g_hh  [ROWS * HID];
__device__ __align__(256) __nv_bfloat16 g_hl  [ROWS * HID];
__device__ __align__(256) __nv_bfloat16 g_qwh [QKV3 * DIM];
__device__ __align__(256) __nv_bfloat16 g_qwl [QKV3 * DIM];
__device__ __align__(256) __nv_bfloat16 g_pwh [DIM * DIM];
__device__ __align__(256) __nv_bfloat16 g_pwl [DIM * DIM];
__device__ __align__(256) __nv_bfloat16 g_f1h [HID * DIM];
__device__ __align__(256) __nv_bfloat16 g_f1l [HID * DIM];
__device__ __align__(256) __nv_bfloat16 g_f2h [DIM * HID];
__device__ __align__(256) __nv_bfloat16 g_f2l [DIM * HID];

// ---------------- helpers ---------------------------------------------------
__device__ __forceinline__ uint32_t smem_u32(const void* p) {
    uint32_t a;
    asm("{ .reg .u64 t; cvta.to.shared.u64 t, %1; cvt.u32.u64 %0, t; }"
        : "=r"(a) : "l"(p));
    return a;
}

__device__ __forceinline__ void ldsm4(uint32_t* r, uint32_t addr) {
    asm volatile("ldmatrix.sync.aligned.m8n8.x4.shared.b16 {%0,%1,%2,%3}, [%4];"
                 : "=r"(r[0]), "=r"(r[1]), "=r"(r[2]), "=r"(r[3]) : "r"(addr));
}

__device__ __forceinline__ void mma16816(float* c, const uint32_t* a,
                                         const uint32_t* b) {
    asm volatile(
        "mma.sync.aligned.m16n8k16.row.col.f32.bf16.bf16.f32 "
        "{%0,%1,%2,%3}, {%4,%5,%6,%7}, {%8,%9}, {%0,%1,%2,%3};"
        : "+f"(c[0]), "+f"(c[1]), "+f"(c[2]), "+f"(c[3])
        : "r"(a[0]), "r"(a[1]), "r"(a[2]), "r"(a[3]), "r"(b[0]), "r"(b[1]));
}

__device__ __forceinline__ uint32_t hipack(float x, float y) {
    return (__float_as_uint(x) >> 16) | (__float_as_uint(y) & 0xFFFF0000u);
}
__device__ __forceinline__ uint32_t lopack(float x, float y) {
    float rx = x - __uint_as_float(__float_as_uint(x) & 0xFFFF0000u);
    float ry = y - __uint_as_float(__float_as_uint(y) & 0xFFFF0000u);
    uint32_t r;
    asm("cvt.rn.bf16x2.f32 %0, %1, %2;" : "=r"(r) : "f"(ry), "f"(rx));
    return r;
}
__device__ __forceinline__ void split4(const float4 v, uint2& h, uint2& l) {
    h.x = hipack(v.x, v.y);
    h.y = hipack(v.z, v.w);
    l.x = lopack(v.x, v.y);
    l.y = lopack(v.z, v.w);
}

#define CP_ASYNC16(dst, src) \
    asm volatile("cp.async.cg.shared.global [%0], [%1], 16;" \
                 :: "r"(dst), "l"(src))
#define CP_COMMIT() asm volatile("cp.async.commit_group;" ::: "memory")
#define CP_WAIT(n)  asm volatile("cp.async.wait_group %0;" :: "n"(n) : "memory")

// ---------------- weight split: fp32 -> bf16 hi/lo ---------------------------
__global__ void __launch_bounds__(256) convert_w(
    const float* __restrict__ w, __nv_bfloat16* __restrict__ wh,
    __nv_bfloat16* __restrict__ wl, int n4)
{
    int i = blockIdx.x * 256 + threadIdx.x;
    if (i >= n4) return;
    float4 v = ((const float4*)w)[i];
    uint2 h, l;
    split4(v, h, l);
    ((uint2*)wh)[i] = h;
    ((uint2*)wl)[i] = l;
}

// ---------------- LayerNorm -> split bf16 output -----------------------------
__global__ void __launch_bounds__(256) ln_split(
    const float* __restrict__ x, const float* __restrict__ w,
    const float* __restrict__ b, __nv_bfloat16* __restrict__ oh,
    __nv_bfloat16* __restrict__ ol)
{
    const int row = blockIdx.x;
    const float* xr = x + (size_t)row * DIM;
    const size_t base = (size_t)row * DIM;
    const int t = threadIdx.x;

    float v0 = xr[t], v1 = xr[t + 256], v2 = xr[t + 512];
    float s  = v0 + v1 + v2;
    float ss = v0 * v0 + v1 * v1 + v2 * v2;

    __shared__ float red[16];
    #pragma unroll
    for (int o = 16; o > 0; o >>= 1) {
        s  += __shfl_xor_sync(0xffffffffu, s,  o);
        ss += __shfl_xor_sync(0xffffffffu, ss, o);
    }
    const int lane = t & 31, wid = t >> 5;
    if (lane == 0) { red[wid] = s; red[8 + wid] = ss; }
    __syncthreads();
    if (t == 0) {
        float a = 0.f, c = 0.f;
        #pragma unroll
        for (int i = 0; i < 8; i++) { a += red[i]; c += red[8 + i]; }
        float mean = a * (1.0f / DIM);
        float var  = c * (1.0f / DIM) - mean * mean;
        red[0] = mean;
        red[1] = rsqrtf(var + 1e-5f);
    }
    __syncthreads();
    const float mean = red[0], rstd = red[1];
    #pragma unroll
    for (int u = 0; u < 3; u++) {
        const int col = t + u * 256;
        const float v = (u == 0 ? v0 : (u == 1 ? v1 : v2));
        float y = (v - mean) * rstd * w[col] + b[col];
        uint32_t bits = __float_as_uint(y);
        ((uint16_t*)oh)[base + col] = (uint16_t)(bits >> 16);
        float rem = y - __uint_as_float(bits & 0xFFFF0000u);
        ol[base + col] = __float2bfloat16(rem);
    }
}

// ---------------- cp.async HMMA split GEMM-NT --------------------------------
// C = A @ W^T + bias (+R fp32) (+GELU); A,W given as bf16 hi/lo in gmem.
// CTA 128x128, BK=32, 2-stage cp.async, 8 warps (4m x 2n), 2 CTAs/SM.
#define CP_PITCH 80u
#define CP_TILE  (128u * CP_PITCH)     // 10240
#define CP_STAGE (4u * CP_TILE)        // Ah Al Wh Wl = 40960
#define CP_SMEM  (2u * CP_STAGE)       // 81920 -> 2 CTAs/SM

// OUTS: 0 = fp32 C, 1 = split bf16 Ch/Cl
template <int ACT, int RES, int OUTS>
__global__ void __launch_bounds__(256, 2) gemm_cp(
    const __nv_bfloat16* __restrict__ Ah, const __nv_bfloat16* __restrict__ Al,
    const __nv_bfloat16* __restrict__ Wh, const __nv_bfloat16* __restrict__ Wl,
    const float* __restrict__ bias, const float* __restrict__ R,
    float* __restrict__ C, __nv_bfloat16* __restrict__ Ch,
    __nv_bfloat16* __restrict__ Cl, int M, int N, int K)
{
    extern __shared__ __align__(16) char sm[];
    const uint32_t sb = smem_u32(sm);

    const int t    = threadIdx.x;
    const int lane = t & 31, wid = t >> 5;
    const int mw   = wid & 3, nw = wid >> 2;
    const int m0   = blockIdx.y * 128, n0 = blockIdx.x * 128;
    const int NC   = K >> 5;

    const int lrow = (t >> 2);        // 0..63
    const int lc   = t & 3;           // 16B chunk within 64B row

    const __nv_bfloat16* srcs[4] = {
        Ah + (size_t)m0 * K, Al + (size_t)m0 * K,
        Wh + (size_t)n0 * K, Wl + (size_t)n0 * K };

    auto issue = [&](uint32_t sbase, int kc) {
        #pragma unroll
        for (int u = 0; u < 8; u++) {
            const int tile = u >> 1;
            const int row  = lrow + (u & 1) * 64;
            const __nv_bfloat16* src =
                srcs[tile] + (size_t)row * K + kc + lc * 8;
            uint32_t dst = sbase + tile * CP_TILE
                         + (uint32_t)row * CP_PITCH + lc * 16;
            CP_ASYNC16(dst, src);
        }
    };

    float cfr[2][8][4];
    #pragma unroll
    for (int i = 0; i < 2; i++)
        #pragma unroll
        for (int j = 0; j < 8; j++)
            #pragma unroll
            for (int k = 0; k < 4; k++) cfr[i][j][k] = 0.f;

    issue(sb, 0);
    CP_COMMIT();

    const uint32_t a_lane = (uint32_t)(mw * 32 + (lane & 15)) * CP_PITCH
                          + ((lane >> 4) * 16);
    const uint32_t b_lane = (uint32_t)(nw * 64 + (lane & 7)
                          + (((lane >> 4) & 1) * 8)) * CP_PITCH
                          + (((lane >> 3) & 1) * 16);

    for (int c = 0; c < NC; c++) {
        CP_WAIT(0);
        __syncthreads();

        // start next stage's loads first so they overlap the MMA section
        if (c + 1 < NC) issue(sb + ((c + 1) & 1) * CP_STAGE, (c + 1) * 32);
        CP_COMMIT();

        const uint32_t stage = sb + (uint32_t)(c & 1) * CP_STAGE;
        #pragma unroll
        for (int ks = 0; ks < 2; ks++) {
            uint32_t ah[2][4], al[2][4];
            #pragma unroll
            for (int mt = 0; mt < 2; mt++) {
                uint32_t aoff = a_lane + (uint32_t)mt * (16 * CP_PITCH)
                              + ks * 32;
                ldsm4(ah[mt], stage + aoff);
                ldsm4(al[mt], stage + CP_TILE + aoff);
            }
            #pragma unroll
            for (int p = 0; p < 4; p++) {
                uint32_t bh[4], bl[4];
                uint32_t boff = b_lane + (uint32_t)p * (16 * CP_PITCH)
                              + ks * 32;
                ldsm4(bh, stage + 2 * CP_TILE + boff);
                ldsm4(bl, stage + 3 * CP_TILE + boff);
                #pragma unroll
                for (int mt = 0; mt < 2; mt++) {
                    #pragma unroll
                    for (int q = 0; q < 2; q++) {
                        float* cc = cfr[mt][2 * p + q];
                        mma16816(cc, ah[mt], &bh[q * 2]);
                        mma16816(cc, ah[mt], &bl[q * 2]);
                        mma16816(cc, al[mt], &bh[q * 2]);
                    }
                }
            }
        }
        __syncthreads();
    }

    // ---- epilogue ----
    const int er0 = m0 + mw * 32 + (lane >> 2);
    const int ec0 = n0 + nw * 64 + (lane & 3) * 2;
    #pragma unroll
    for (int mt = 0; mt < 2; mt++) {
        #pragma unroll
        for (int nt = 0; nt < 8; nt++) {
            const int col = ec0 + nt * 8;
            const float2 bv = *(const float2*)(bias + col);
            #pragma unroll
            for (int half = 0; half < 2; half++) {
                const int row = er0 + mt * 16 + half * 8;
                const size_t off = (size_t)row * N + col;
                float vx = cfr[mt][nt][half * 2 + 0] + bv.x;
                float vy = cfr[mt][nt][half * 2 + 1] + bv.y;
                if (RES) {
                    const float2 rv = *(const float2*)(R + off);
                    vx += rv.x; vy += rv.y;
                }
                if (ACT) {
                    vx = 0.5f * vx * (1.0f + erff(vx * 0.70710678118654752f));
                    vy = 0.5f * vy * (1.0f + erff(vy * 0.70710678118654752f));
                }
                if (OUTS == 0) {
                    *(float2*)(C + off) = make_float2(vx, vy);
                } else {
                    *(uint32_t*)(Ch + off) = hipack(vx, vy);
                    *(uint32_t*)(Cl + off) = lopack(vx, vy);
                }
            }
        }
    }
}

// ---------------- HMMA flash attention (bf16 hi/lo split) -------------------
#define FP_P    144u
#define FQ_H    0u
#define FQ_L    (FQ_H + 128u * FP_P)
#define FK_H    (FQ_L + 128u * FP_P)
#define FK_L    (FK_H + 64u * FP_P)
#define FV_H    (FK_L + 64u * FP_P)
#define FV_L    (FV_H + 64u * FP_P)
#define FL_SMEM (FV_L + 64u * FP_P)        // 73728

__global__ void __launch_bounds__(256, 1) flash_mma(
    const float* __restrict__ qkv, __nv_bfloat16* __restrict__ atth,
    __nv_bfloat16* __restrict__ attl)
{
    extern __shared__ __align__(16) char sm[];
    const uint32_t sb = smem_u32(sm);

    const int bh = blockIdx.y;
    const int b  = bh / NH, h = bh % NH;
    const int q0 = blockIdx.x * 128;
    const int t  = threadIdx.x, lane = t & 31, wid = t >> 5;

    #pragma unroll
    for (int u = 0; u < 8; u++) {
        int i = t + u * 256, row = i >> 4, c4 = i & 15;
        float4 v = *(const float4*)(qkv + (size_t)(b * SEQ + q0 + row) * QKV3
                                    + h * HD + c4 * 4);
        uint2 hh, ll;
        split4(v, hh, ll);
        uint32_t off = (uint32_t)row * FP_P + c4 * 8;
        *(uint2*)(sm + FQ_H + off) = hh;
        *(uint2*)(sm + FQ_L + off) = ll;
    }

    float4 rk[4], rv[4];
    {
        #pragma unroll
        for (int u = 0; u < 4; u++) {
            int i = t + u * 256, key = i >> 4, c4 = i & 15;
            const size_t rowb = (size_t)(b * SEQ + key) * QKV3 + h * HD + c4 * 4;
            rk[u] = *(const float4*)(qkv + rowb + DIM);
            rv[u] = *(const float4*)(qkv + rowb + 2 * DIM);
        }
    }
    __syncthreads();

    uint32_t qh[4][4], ql[4][4];
    {
        const uint32_t a_lane = (uint32_t)(wid * 16 + (lane & 15)) * FP_P
                              + ((lane >> 4) * 16);
        #pragma unroll
        for (int ks = 0; ks < 4; ks++) {
            ldsm4(qh[ks], sb + FQ_H + a_lane + ks * 32);
            ldsm4(ql[ks], sb + FQ_L + a_lane + ks * 32);
        }
    }

    #pragma unroll
    for (int u = 0; u < 4; u++) {
        int i = t + u * 256, key = i >> 4, c4 = i & 15;
        uint2 hh, ll;
        split4(rk[u], hh, ll);
        uint32_t off = (uint32_t)key * FP_P + c4 * 8;
        *(uint2*)(sm + FK_H + off) = hh;
        *(uint2*)(sm + FK_L + off) = ll;
        const float vv[4] = { rv[u].x, rv[u].y, rv[u].z, rv[u].w };
        #pragma unroll
        for (int j = 0; j < 4; j++) {
            int d = c4 * 4 + j;
            uint32_t bits = __float_as_uint(vv[j]);
            *(uint16_t*)(sm + FV_H + (uint32_t)d * FP_P + key * 2) =
                (uint16_t)(bits >> 16);
            float rem = vv[j] - __uint_as_float(bits & 0xFFFF0000u);
            *(__nv_bfloat16*)(sm + FV_L + (uint32_t)d * FP_P + key * 2) =
                __float2bfloat16(rem);
        }
    }
    __syncthreads();

    float mr1 = -1e30f, mr2 = -1e30f, lr1 = 0.f, lr2 = 0.f;
    float o[8][4];
    #pragma unroll
    for (int f = 0; f < 8; f++)
        #pragma unroll
        for (int j = 0; j < 4; j++) o[f][j] = 0.f;

    const uint32_t bK = (uint32_t)((lane & 7) + ((lane >> 4) & 1) * 8) * FP_P
                      + ((lane >> 3) & 1) * 16;

    const int NT = SEQ / 64;
    for (int c = 0; c < NT; c++) {
        if (c + 1 < NT) {
            const int k0 = (c + 1) * 64;
            #pragma unroll
            for (int u = 0; u < 4; u++) {
                int i = t + u * 256, key = i >> 4, c4 = i & 15;
                const size_t rowb = (size_t)(b * SEQ + k0 + key) * QKV3
                                  + h * HD + c4 * 4;
                rk[u] = *(const float4*)(qkv + rowb + DIM);
                rv[u] = *(const float4*)(qkv + rowb + 2 * DIM);
            }
        }

        float sf[8][4];
        #pragma unroll
        for (int f = 0; f < 8; f++)
            #pragma unroll
            for (int j = 0; j < 4; j++) sf[f][j] = 0.f;

        #pragma unroll
        for (int p = 0; p < 4; p++) {
            #pragma unroll
            for (int ks = 0; ks < 4; ks++) {
                uint32_t bhf[4], blf[4];
                uint32_t boff = bK + (uint32_t)p * (16 * FP_P) + ks * 32;
                ldsm4(bhf, sb + FK_H + boff);
                ldsm4(blf, sb + FK_L + boff);
                #pragma unroll
                for (int q = 0; q < 2; q++) {
                    float* cc = sf[2 * p + q];
                    mma16816(cc, qh[ks], &bhf[q * 2]);
                    mma16816(cc, qh[ks], &blf[q * 2]);
                    mma16816(cc, ql[ks], &bhf[q * 2]);
                }
            }
        }

        float m1 = -1e30f, m2 = -1e30f;
        #pragma unroll
        for (int f = 0; f < 8; f++) {
            sf[f][0] *= 0.125f; sf[f][1] *= 0.125f;
            sf[f][2] *= 0.125f; sf[f][3] *= 0.125f;
            m1 = fmaxf(m1, fmaxf(sf[f][0], sf[f][1]));
            m2 = fmaxf(m2, fmaxf(sf[f][2], sf[f][3]));
        }
        m1 = fmaxf(m1, __shfl_xor_sync(0xffffffffu, m1, 1));
        m1 = fmaxf(m1, __shfl_xor_sync(0xffffffffu, m1, 2));
        m2 = fmaxf(m2, __shfl_xor_sync(0xffffffffu, m2, 1));
        m2 = fmaxf(m2, __shfl_xor_sync(0xffffffffu, m2, 2));

        const float mn1 = fmaxf(mr1, m1), mn2 = fmaxf(mr2, m2);
        const float corr1 = __expf(mr1 - mn1), corr2 = __expf(mr2 - mn2);
        float r1 = 0.f, r2 = 0.f;
        #pragma unroll
        for (int f = 0; f < 8; f++) {
            sf[f][0] = __expf(sf[f][0] - mn1);
            sf[f][1] = __expf(sf[f][1] - mn1);
            sf[f][2] = __expf(sf[f][2] - mn2);
            sf[f][3] = __expf(sf[f][3] - mn2);
            r1 += sf[f][0] + sf[f][1];
            r2 += sf[f][2] + sf[f][3];
        }
        r1 += __shfl_xor_sync(0xffffffffu, r1, 1);
        r1 += __shfl_xor_sync(0xffffffffu, r1, 2);
        r2 += __shfl_xor_sync(0xffffffffu, r2, 1);
        r2 += __shfl_xor_sync(0xffffffffu, r2, 2);
        lr1 = lr1 * corr1 + r1;
        lr2 = lr2 * corr2 + r2;
        mr1 = mn1; mr2 = mn2;
        #pragma unroll
        for (int f = 0; f < 8; f++) {
            o[f][0] *= corr1; o[f][1] *= corr1;
            o[f][2] *= corr2; o[f][3] *= corr2;
        }

        #pragma unroll
        for (int ks2 = 0; ks2 < 4; ks2++) {
            const int f = 2 * ks2;
            uint32_t ph[4], pl[4];
            ph[0] = hipack(sf[f][0],     sf[f][1]);
            ph[1] = hipack(sf[f][2],     sf[f][3]);
            ph[2] = hipack(sf[f + 1][0], sf[f + 1][1]);
            ph[3] = hipack(sf[f + 1][2], sf[f + 1][3]);
            pl[0] = lopack(sf[f][0],     sf[f][1]);
            pl[1] = lopack(sf[f][2],     sf[f][3]);
            pl[2] = lopack(sf[f + 1][0], sf[f + 1][1]);
            pl[3] = lopack(sf[f + 1][2], sf[f + 1][3]);
            #pragma unroll
            for (int p = 0; p < 4; p++) {
                uint32_t vh[4], vl[4];
                uint32_t boff = bK + (uint32_t)p * (16 * FP_P) + ks2 * 32;
                ldsm4(vh, sb + FV_H + boff);
                ldsm4(vl, sb + FV_L + boff);
                #pragma unroll
                for (int q = 0; q < 2; q++) {
                    float* cc = o[2 * p + q];
                    mma16816(cc, ph, &vh[q * 2]);
                    mma16816(cc, ph, &vl[q * 2]);
                    mma16816(cc, pl, &vh[q * 2]);
                }
            }
        }
        __syncthreads();

        if (c + 1 < NT) {
            #pragma unroll
            for (int u = 0; u < 4; u++) {
                int i = t + u * 256, key = i >> 4, c4 = i & 15;
                uint2 hh, ll;
                split4(rk[u], hh, ll);
                uint32_t off = (uint32_t)key * FP_P + c4 * 8;
                *(uint2*)(sm + FK_H + off) = hh;
                *(uint2*)(sm + FK_L + off) = ll;
                const float vv[4] = { rv[u].x, rv[u].y, rv[u].z, rv[u].w };
                #pragma unroll
                for (int j = 0; j < 4; j++) {
                    int d = c4 * 4 + j;
                    uint32_t bits = __float_as_uint(vv[j]);
                    *(uint16_t*)(sm + FV_H + (uint32_t)d * FP_P + key * 2) =
                        (uint16_t)(bits >> 16);
                    float rem = vv[j] - __uint_as_float(bits & 0xFFFF0000u);
                    *(__nv_bfloat16*)(sm + FV_L + (uint32_t)d * FP_P + key * 2) =
                        __float2bfloat16(rem);
                }
            }
            __syncthreads();
        }
    }

    const float il1 = 1.0f / lr1, il2 = 1.0f / lr2;
    const int row1 = b * SEQ + q0 + wid * 16 + (lane >> 2);
    #pragma unroll
    for (int f = 0; f < 8; f++) {
        const int col = h * HD + f * 8 + (lane & 3) * 2;
        const size_t o1 = (size_t)row1 * DIM + col;
        const size_t o2 = (size_t)(row1 + 8) * DIM + col;
        float ax = o[f][0] * il1, ay = o[f][1] * il1;
        float bx = o[f][2] * il2, by = o[f][3] * il2;
        *(uint32_t*)(atth + o1) = hipack(ax, ay);
        *(uint32_t*)(attl + o1) = lopack(ax, ay);
        *(uint32_t*)(atth + o2) = hipack(bx, by);
        *(uint32_t*)(attl + o2) = lopack(bx, by);
    }
}

// ---------------------------------------------------------------------------
extern "C" void kernel_launch(void* const* d_in, const int* in_sizes, int n_in,
                              void* d_out, int out_size)
{
    const float* x      = (const float*)d_in[0];
    const float* ln1_w  = (const float*)d_in[1];
    const float* ln1_b  = (const float*)d_in[2];
    const float* qkv_w  = (const float*)d_in[3];
    const float* qkv_b  = (const float*)d_in[4];
    const float* proj_w = (const float*)d_in[5];
    const float* proj_b = (const float*)d_in[6];
    const float* ln2_w  = (const float*)d_in[7];
    const float* ln2_b  = (const float*)d_in[8];
    const float* fc1_w  = (const float*)d_in[9];
    const float* fc1_b  = (const float*)d_in[10];
    const float* fc2_w  = (const float*)d_in[11];
    const float* fc2_b  = (const float*)d_in[12];
    float* out = (float*)d_out;

    float *p_qkv, *p_res;
    __nv_bfloat16 *p_lnh, *p_lnl, *p_atth, *p_attl, *p_hh, *p_hl;
    __nv_bfloat16 *p_qwh, *p_qwl, *p_pwh, *p_pwl, *p_f1h, *p_f1l, *p_f2h, *p_f2l;
    cudaGetSymbolAddress((void**)&p_qkv,  g_qkv);
    cudaGetSymbolAddress((void**)&p_res,  g_res);
    cudaGetSymbolAddress((void**)&p_lnh,  g_lnh);
    cudaGetSymbolAddress((void**)&p_lnl,  g_lnl);
    cudaGetSymbolAddress((void**)&p_atth, g_atth);
    cudaGetSymbolAddress((void**)&p_attl, g_attl);
    cudaGetSymbolAddress((void**)&p_hh,   g_hh);
    cudaGetSymbolAddress((void**)&p_hl,   g_hl);
    cudaGetSymbolAddress((void**)&p_qwh,  g_qwh);
    cudaGetSymbolAddress((void**)&p_qwl,  g_qwl);
    cudaGetSymbolAddress((void**)&p_pwh,  g_pwh);
    cudaGetSymbolAddress((void**)&p_pwl,  g_pwl);
    cudaGetSymbolAddress((void**)&p_f1h,  g_f1h);
    cudaGetSymbolAddress((void**)&p_f1l,  g_f1l);
    cudaGetSymbolAddress((void**)&p_f2h,  g_f2h);
    cudaGetSymbolAddress((void**)&p_f2l,  g_f2l);

    cudaFuncSetAttribute(flash_mma,
                         cudaFuncAttributeMaxDynamicSharedMemorySize, FL_SMEM);
    cudaFuncSetAttribute(gemm_cp<0, 0, 0>,
                         cudaFuncAttributeMaxDynamicSharedMemorySize, CP_SMEM);
    cudaFuncSetAttribute(gemm_cp<0, 1, 0>,
                         cudaFuncAttributeMaxDynamicSharedMemorySize, CP_SMEM);
    cudaFuncSetAttribute(gemm_cp<1, 0, 1>,
                         cudaFuncAttributeMaxDynamicSharedMemorySize, CP_SMEM);

    // 0) split all weights up-front
    {
        int n4;
        n4 = QKV3 * DIM / 4;
        convert_w<<<(n4 + 255) / 256, 256>>>(qkv_w, p_qwh, p_qwl, n4);
        n4 = DIM * DIM / 4;
        convert_w<<<(n4 + 255) / 256, 256>>>(proj_w, p_pwh, p_pwl, n4);
        n4 = HID * DIM / 4;
        convert_w<<<(n4 + 255) / 256, 256>>>(fc1_w, p_f1h, p_f1l, n4);
        n4 = DIM * HID / 4;
        convert_w<<<(n4 + 255) / 256, 256>>>(fc2_w, p_f2h, p_f2l, n4);
    }

    // 1) ln1(x) -> split
    ln_split<<<ROWS, 256>>>(x, ln1_w, ln1_b, p_lnh, p_lnl);
    // 2) qkv = ln1 @ qkv_w^T + qkv_b -> fp32 (flash input)
    gemm_cp<0, 0, 0><<<dim3(QKV3 / 128, ROWS / 128), 256, CP_SMEM>>>(
        p_lnh, p_lnl, p_qwh, p_qwl, qkv_b, nullptr,
        p_qkv, nullptr, nullptr, ROWS, QKV3, DIM);
    // 3) attention -> split att
    flash_mma<<<dim3(SEQ / 128, 4 * NH), 256, FL_SMEM>>>(p_qkv, p_atth, p_attl);
    // 4) x1 = att @ proj_w^T + proj_b + x -> fp32 res
    gemm_cp<0, 1, 0><<<dim3(DIM / 128, ROWS / 128), 256, CP_SMEM>>>(
        p_atth, p_attl, p_pwh, p_pwl, proj_b, x,
        p_res, nullptr, nullptr, ROWS, DIM, DIM);
    // 5) ln2(x1) -> split
    ln_split<<<ROWS, 256>>>(p_res, ln2_w, ln2_b, p_lnh, p_lnl);
    // 6) h = gelu(ln2 @ fc1_w^T + fc1_b) -> split
    gemm_cp<1, 0, 1><<<dim3(HID / 128, ROWS / 128), 256, CP_SMEM>>>(
        p_lnh, p_lnl, p_f1h, p_f1l, fc1_b, nullptr,
        nullptr, p_hh, p_hl, ROWS, HID, DIM);
    // 7) out = h @ fc2_w^T + fc2_b + x1
    gemm_cp<0, 1, 0><<<dim3(DIM / 128, ROWS / 128), 256, CP_SMEM>>>(
        p_hh, p_hl, p_f2h, p_f2l, fc2_b, p_res,
        out, nullptr, nullptr, ROWS, DIM, HID);
}